// round 8
// baseline (speedup 1.0000x reference)
#include <cuda_runtime.h>
#include <math.h>

#define NPROB 4096
#define TPB   256
#define ITERS 80
static constexpr float SIGMA_  = 1e-6f;
static constexpr float EPSLMO_ = 1e-4f;

__device__ float g_xfeas[NPROB * 64];

#define FMA2(d,a,b)  asm("fma.rn.f32x2 %0, %1, %2, %0;" : "+l"(d) : "l"(a), "l"(b))
#define PACK2(d,x,y) asm("mov.b64 %0, {%1, %2};" : "=l"(d) : "f"(x), "f"(y))
#define UNPK2(x,y,v) asm("mov.b64 {%0, %1}, %2;" : "=f"(x), "=f"(y) : "l"(v))

__device__ __forceinline__ float dot4(float4 a, float4 b){
    return a.x*b.x + a.y*b.y + a.z*b.z + a.w*b.w;
}
__device__ __forceinline__ float dotA(const float* sA, int i, const float* v){
    const float4* a4 = (const float4*)(sA + i*68);
    const float4* v4 = (const float4*)v;
    float s = 0.f;
#pragma unroll
    for (int q = 0; q < 16; ++q) s += dot4(a4[q], v4[q]);
    return s;
}

// ---------------------------------------------------------------------------
// Register-resident GJ inverse of M = diag*I + A^T A (64x64), result -> sM.
// Thread t: row gi = t&63, cols [j0, j0+16), j0 = (t>>6)*16, in R[16].
// Pivot row chunks are consumed immediately (live pr = 1 float4) to keep
// register pressure under the 3-CTA (85 reg) cap.
// ---------------------------------------------------------------------------
__device__ __forceinline__ void gj64_reg(const float* sA, float* sM, float diag,
                                         float* bufRow, float* bufCol, float* bufPinv)
{
    const int t  = threadIdx.x;
    const int gi = t & 63;
    const int cb = t >> 6;
    const int j0 = cb << 4;

    float R[16];
#pragma unroll
    for (int l = 0; l < 16; ++l) R[l] = 0.f;
    for (int r = 0; r < 32; ++r){
        float  ag = sA[r*68 + gi];
        float4 a0 = *(const float4*)(sA + r*68 + j0);
        float4 a1 = *(const float4*)(sA + r*68 + j0 + 4);
        float4 a2 = *(const float4*)(sA + r*68 + j0 + 8);
        float4 a3 = *(const float4*)(sA + r*68 + j0 + 12);
        R[0]+=ag*a0.x; R[1]+=ag*a0.y; R[2]+=ag*a0.z; R[3]+=ag*a0.w;
        R[4]+=ag*a1.x; R[5]+=ag*a1.y; R[6]+=ag*a1.z; R[7]+=ag*a1.w;
        R[8]+=ag*a2.x; R[9]+=ag*a2.y; R[10]+=ag*a2.z; R[11]+=ag*a2.w;
        R[12]+=ag*a3.x; R[13]+=ag*a3.y; R[14]+=ag*a3.z; R[15]+=ag*a3.w;
    }
    if ((gi >> 4) == cb){
#pragma unroll
        for (int l = 0; l < 16; ++l) if ((gi & 15) == l) R[l] += diag;
    }
    if (gi == 0){
        *(float4*)(bufRow + j0)      = make_float4(R[0],R[1],R[2],R[3]);
        *(float4*)(bufRow + j0 + 4)  = make_float4(R[4],R[5],R[6],R[7]);
        *(float4*)(bufRow + j0 + 8)  = make_float4(R[8],R[9],R[10],R[11]);
        *(float4*)(bufRow + j0 + 12) = make_float4(R[12],R[13],R[14],R[15]);
        if (cb == 0) bufPinv[0] = __frcp_rn(R[0]);
    }
    if (cb == 0) bufCol[gi] = R[0];
    __syncthreads();

    for (int ko = 0; ko < 4; ++ko){
#pragma unroll
        for (int ki = 0; ki < 16; ++ki){
            const int k = ko*16 + ki;
            const int b = ki & 1;
            float pinv = bufPinv[b];
            float pc   = bufCol[b*64 + gi];
            const bool isk = (gi == k);
            float fac = isk ? pinv : (-pc * pinv);
            // R = isk ? pr*pinv : R - cp*pr   ==  R*(isk?0:1) + fac*pr
#pragma unroll
            for (int q = 0; q < 4; ++q){
                float4 p = *(const float4*)(bufRow + b*64 + j0 + 4*q);
                if (isk){
                    R[4*q+0] = p.x*fac; R[4*q+1] = p.y*fac;
                    R[4*q+2] = p.z*fac; R[4*q+3] = p.w*fac;
                } else {
                    R[4*q+0] += p.x*fac; R[4*q+1] += p.y*fac;
                    R[4*q+2] += p.z*fac; R[4*q+3] += p.w*fac;
                }
            }
            if (ko == cb) R[ki] = isk ? pinv : fac;
            if (k < 63){
                const int kn  = k + 1;
                const int bn  = kn & 1;
                const int kol = (ki == 15) ? (ko + 1) : ko;
                const int lnl = (ki + 1) & 15;
                if (gi == kn){
                    *(float4*)(bufRow + bn*64 + j0)      = make_float4(R[0],R[1],R[2],R[3]);
                    *(float4*)(bufRow + bn*64 + j0 + 4)  = make_float4(R[4],R[5],R[6],R[7]);
                    *(float4*)(bufRow + bn*64 + j0 + 8)  = make_float4(R[8],R[9],R[10],R[11]);
                    *(float4*)(bufRow + bn*64 + j0 + 12) = make_float4(R[12],R[13],R[14],R[15]);
                    if (kol == cb) bufPinv[bn] = __frcp_rn(R[lnl]);
                }
                if (kol == cb) bufCol[bn*64 + gi] = R[lnl];
            }
            __syncthreads();
        }
    }
    *(float4*)(sM + gi*68 + j0)      = make_float4(R[0],R[1],R[2],R[3]);
    *(float4*)(sM + gi*68 + j0 + 4)  = make_float4(R[4],R[5],R[6],R[7]);
    *(float4*)(sM + gi*68 + j0 + 8)  = make_float4(R[8],R[9],R[10],R[11]);
    *(float4*)(sM + gi*68 + j0 + 12) = make_float4(R[12],R[13],R[14],R[15]);
    __syncthreads();
}

// T (64x32, stride 36) = N * A^T
__device__ __forceinline__ void gemmT(const float* sM, const float* sA, float* sT)
{
    const int t  = threadIdx.x;
    const int i0 = (t >> 4) << 2;
    const int r0 = (t & 15) << 1;
    float acc[4][2] = {};
    for (int j = 0; j < 64; j += 4){
        float4 a0 = *(const float4*)(sA + r0*68     + j);
        float4 a1 = *(const float4*)(sA + (r0+1)*68 + j);
#pragma unroll
        for (int a = 0; a < 4; ++a){
            float4 nv = *(const float4*)(sM + (i0+a)*68 + j);
            acc[a][0] += dot4(nv, a0);
            acc[a][1] += dot4(nv, a1);
        }
    }
#pragma unroll
    for (int a = 0; a < 4; ++a){
        sT[(i0+a)*36 + r0]     = acc[a][0];
        sT[(i0+a)*36 + r0 + 1] = acc[a][1];
    }
}

// S (32x32, stride 36) = A * T
__device__ __forceinline__ void gemmS(const float* sA, const float* sT, float* sS)
{
    const int t  = threadIdx.x;
    const int r  = t >> 3;
    const int cb = (t & 7) << 2;
    float4 acc = make_float4(0.f,0.f,0.f,0.f);
    for (int i = 0; i < 64; ++i){
        float av  = sA[r*68 + i];
        float4 tv = *(const float4*)(sT + i*36 + cb);
        acc.x += av*tv.x; acc.y += av*tv.y; acc.z += av*tv.z; acc.w += av*tv.w;
    }
    *(float4*)(sS + r*36 + cb) = acc;
}

// ======================= ANCHOR: d=68 (Schur), K=100 (pad 104) ==============
__device__ __forceinline__ float gA(int r, int c, const float* sM, const float* sT,
                                    const float* sS, const float* sW, const float* sV,
                                    const float* sXi)
{
    if (c >= 100) return 0.f;
    if (r < 64){
        if (c < 64) return sM[r*68 + c];
        if (c < 92) return sT[r*36 + (c-64)];
        if (c < 96) return sT[r*36 + 28 + (c-92)] + sW[r*4 + (c-92)];
        return -sW[r*4 + (c-96)];
    }
    if (r < 92){ int i = r-64;
        if (c < 64) return sT[c*36 + i];
        if (c < 92) return sS[i*36 + (c-64)];
        if (c < 96) return sS[i*36 + 28 + (c-92)] + sV[i*4 + (c-92)];
        return -sV[i*4 + (c-96)];
    }
    if (r < 96){ int m = r-92, i = 28+m;
        if (c < 64) return sT[c*36 + i] + sW[c*4 + m];
        if (c < 92) return sS[i*36 + (c-64)] + sV[(c-64)*4 + m];
        if (c < 96){ int j = c-92;
            return sS[i*36 + 28 + j] + sV[i*4 + j] + sV[(28+j)*4 + m] + sXi[m*4 + j]; }
        { int j = c-96; return -sV[i*4 + j] - sXi[m*4 + j]; }
    }
    { int m = r-96;
        if (c < 64) return -sW[c*4 + m];
        if (c < 92) return -sV[(c-64)*4 + m];
        if (c < 96){ int j = c-92; return -sV[(28+j)*4 + m] - sXi[m*4 + j]; }
        { int j = c-96; return sXi[m*4 + j]; }
    }
}

__global__ void __launch_bounds__(TPB, 3)
anchor_kernel(const float* __restrict__ xr, const float* __restrict__ Ain,
              const float* __restrict__ bin)
{
    extern __shared__ float sm[];
    float* sA  = sm;             // 32*68
    float* sM  = sA  + 2176;     // 64*68
    float* sT  = sM  + 4352;     // 64*36
    float* sS  = sT  + 2304;     // 32*36
    float* sY  = sS  + 1152;     // 64*4
    float* sW  = sY  + 256;      // 64*4
    float* sU  = sW  + 256;      // 32*4
    float* sV  = sU  + 128;      // 32*4
    float* sXi = sV  + 128;      // 16
    float* sv  = sXi + 16;       // 2*104
    float* su0 = sv  + 208;      // 68
    float* sdx = su0 + 68;       // 68
    float* sxr = sdx + 68;       // 64
    float* bR  = sxr + 64;       // 128
    float* bC  = bR  + 128;      // 128
    float* bP  = bC  + 128;      // 2 + pad

    const int p = blockIdx.x;
    const int t = threadIdx.x;
    const float* Ap = Ain + (size_t)p * 2048;
    const float* bp = bin + (size_t)p * 32;

    for (int e = t; e < 2048; e += TPB) sA[(e>>6)*68 + (e&63)] = Ap[e];
    if (t < 64) sxr[t] = xr[(size_t)p*64 + t];
    if (t >= 64 && t < 72){ int q = t-64; sv[100 + (q&3) + (q>>2)*104] = 0.f; }
    __syncthreads();

    gj64_reg(sA, sM, 2.0f + SIGMA_, bR, bC, bP);
    gemmT(sM, sA, sT);
    __syncthreads();
    gemmS(sA, sT, sS);
    __syncthreads();

    if (t == 0){
        float X[4][4];
        for (int m = 0; m < 4; ++m)
            for (int j = 0; j < 4; ++j)
                X[m][j] = ((m==j) ? (4.0f+SIGMA_) : 0.f) - sS[(28+m)*36 + 28 + j];
        for (int k = 0; k < 4; ++k){
            float pinv = 1.0f / X[k][k];
            for (int j = 0; j < 4; ++j) if (j != k) X[k][j] *= pinv;
            X[k][k] = pinv;
            for (int i = 0; i < 4; ++i) if (i != k){
                float f = X[i][k];
                for (int j = 0; j < 4; ++j) if (j != k) X[i][j] -= f * X[k][j];
                X[i][k] = -f * pinv;
            }
        }
        for (int m = 0; m < 4; ++m)
            for (int j = 0; j < 4; ++j) sXi[m*4+j] = X[m][j];
    }
    __syncthreads();
    if (t < 64){
        float y[4];
#pragma unroll
        for (int m = 0; m < 4; ++m){ y[m] = -sT[t*36 + 28 + m]; sY[t*4+m] = y[m]; }
#pragma unroll
        for (int m = 0; m < 4; ++m){
            float a = 0.f;
#pragma unroll
            for (int j = 0; j < 4; ++j) a += y[j] * sXi[j*4+m];
            sW[t*4+m] = a;
        }
    } else if (t < 96){
        int r = t - 64;
        float u[4];
#pragma unroll
        for (int m = 0; m < 4; ++m){ u[m] = -sS[r*36 + 28 + m]; sU[r*4+m] = u[m]; }
#pragma unroll
        for (int m = 0; m < 4; ++m){
            float a = 0.f;
#pragma unroll
            for (int j = 0; j < 4; ++j) a += u[j] * sXi[j*4+m];
            sV[r*4+m] = a;
        }
    }
    __syncthreads();
    for (int e = t; e < 4096; e += TPB){
        int i = e >> 6, j = e & 63; float a = 0.f;
#pragma unroll
        for (int m = 0; m < 4; ++m) a += sW[i*4+m] * sY[j*4+m];
        sM[i*68 + j] += a;
    }
    for (int e = t; e < 2048; e += TPB){
        int i = e >> 5, a0 = e & 31; float a = 0.f;
#pragma unroll
        for (int m = 0; m < 4; ++m) a += sW[i*4+m] * sU[a0*4+m];
        sT[i*36 + a0] += a;
    }
    for (int e = t; e < 1024; e += TPB){
        int r = e >> 5, c = e & 31; float a = 0.f;
#pragma unroll
        for (int m = 0; m < 4; ++m) a += sV[r*4+m] * sU[c*4+m];
        sS[r*36 + c] += a;
    }
    __syncthreads();
    if (t < 64) su0[t] = dotA(sM, t, sxr);
    else if (t < 68){
        int m = t - 64; float a = 0.f;
        for (int j = 0; j < 64; ++j) a -= sW[j*4+m] * sxr[j];
        su0[64+m] = a;
    }
    __syncthreads();

    const int row = t >> 1, h = t & 1;
    float lo = 0.f, hi = 0.f, cx0 = 0.f;
    if (t < 200){
        if (row < 64){ lo = 0.f; hi = INFINITY; cx0 = su0[row]; }
        else if (row < 92){ int i = row-64; lo = -INFINITY; hi = bp[i]; cx0 = dotA(sA, i, su0); }
        else if (row < 96){ int m = row-92; int i = 28+m;
            lo = -INFINITY; hi = bp[i]; cx0 = dotA(sA, i, su0) - su0[64+m]; }
        else { int m = row-96; lo = 0.f; hi = INFINITY; cx0 = su0[64+m]; }
    }
    unsigned long long G2[26];
    if (t < 200){
#pragma unroll
        for (int c2 = 0; c2 < 26; ++c2){
            float g0 = gA(row, h*52 + 2*c2,     sM, sT, sS, sW, sV, sXi);
            float g1 = gA(row, h*52 + 2*c2 + 1, sM, sT, sS, sW, sV, sXi);
            PACK2(G2[c2], g0, g1);
        }
    }
    __syncthreads();

    float z = fminf(fmaxf(0.f, lo), hi), y = 0.f;
    for (int it = 0; it < ITERS; ++it){
        float* vb = sv + (it & 1) * 104;
        if (t < 200 && h == 0) vb[row] = z - y;
        __syncthreads();
        const ulonglong2* v2 = (const ulonglong2*)vb + h*13;
        unsigned long long a0 = 0ull, a1 = 0ull, a2 = 0ull, a3 = 0ull;
#pragma unroll
        for (int c = 0; c < 13; ++c){
            ulonglong2 vv = v2[c];
            if (c & 1){ FMA2(a2, G2[2*c], vv.x); FMA2(a3, G2[2*c+1], vv.y); }
            else      { FMA2(a0, G2[2*c], vv.x); FMA2(a1, G2[2*c+1], vv.y); }
        }
        float x0, x1, x2, x3, x4, x5, x6, x7;
        UNPK2(x0, x1, a0); UNPK2(x2, x3, a1); UNPK2(x4, x5, a2); UNPK2(x6, x7, a3);
        float acc = ((x0+x1)+(x2+x3)) + ((x4+x5)+(x6+x7));
        acc += __shfl_xor_sync(0xFFFFFFFFu, acc, 1);
        float Cx = cx0 + acc;
        float zn = fminf(fmaxf(Cx + y, lo), hi);
        y += Cx - zn; z = zn;
    }
    __syncthreads();

    const float* vl = sv + ((ITERS-1) & 1) * 104;
    if (t < 64){
        float a = vl[t];
        for (int r = 0; r < 28; ++r) a += sA[r*68 + t] * vl[64+r];
#pragma unroll
        for (int r = 28; r < 32; ++r) a += sA[r*68 + t] * vl[92 + (r-28)];
        sdx[t] = a;
    } else if (t < 68){
        int m = t - 64; sdx[64+m] = vl[96+m] - vl[92+m];
    }
    __syncthreads();
    if (t < 64){
        float a = su0[t] + dotA(sM, t, sdx);
#pragma unroll
        for (int m = 0; m < 4; ++m) a -= sW[t*4+m] * sdx[64+m];
        g_xfeas[(size_t)p*64 + t] = a;
    }
}

// ======================= LMO: d=64, K=96 ====================================
__global__ void __launch_bounds__(TPB, 3)
lmo_kernel(const float* __restrict__ Ain, const float* __restrict__ bin,
           const float* __restrict__ W1, const float* __restrict__ w2,
           float* __restrict__ out)
{
    extern __shared__ float sm[];
    float* sA  = sm;             // 32*68 (normalized)
    float* sM  = sA  + 2176;     // 64*68
    float* sT  = sM  + 4352;     // 64*36
    float* sS  = sT  + 2304;     // 32*36
    float* sv  = sS  + 1152;     // 2*96
    float* su0 = sv  + 192;      // 64
    float* sd  = su0 + 64;       // 64
    float* sx  = sd  + 64;       // 64
    float* shb = sx  + 64;       // 256
    float* sg  = shb + 256;      // 64
    float* srv = sg  + 64;       // 32
    float* bR  = srv + 32;       // 128
    float* bC  = bR  + 128;      // 128
    float* bP  = bC  + 128;      // 2 + pad

    const int p = blockIdx.x;
    const int t = threadIdx.x;
    const float* Ap = Ain + (size_t)p * 2048;
    const float* bp = bin + (size_t)p * 32;

    for (int e = t; e < 2048; e += TPB) sA[(e>>6)*68 + (e&63)] = Ap[e];
    if (t < 64) sx[t] = g_xfeas[(size_t)p*64 + t];
    __syncthreads();

    if (t < 32){
        float ss = 0.f;
        const float* Ar = sA + t*68;
        for (int i = 0; i < 64; ++i) ss += Ar[i]*Ar[i];
        srv[t] = 1.0f / fmaxf(sqrtf(ss), 1e-12f);
    }
    {
        float a = 0.f;
        for (int i = 0; i < 64; ++i) a += sx[i] * W1[i*256 + t];
        float hh = tanhf(a);
        shb[t] = (1.f - hh*hh) * w2[t];
    }
    __syncthreads();
    for (int e = t; e < 2048; e += TPB){
        int r = e >> 6;
        sA[r*68 + (e&63)] *= srv[r];
    }
    {
        int wid = t >> 5, lane = t & 31;
        for (int rr = 0; rr < 8; ++rr){
            int i = wid*8 + rr;
            const float* Wr = W1 + i*256;
            float a = 0.f;
#pragma unroll
            for (int k = 0; k < 8; ++k) a += Wr[k*32 + lane] * shb[k*32 + lane];
#pragma unroll
            for (int o = 16; o; o >>= 1) a += __shfl_xor_sync(0xFFFFFFFFu, a, o);
            if (lane == 0) sg[i] = a;
        }
    }
    __syncthreads();

    gj64_reg(sA, sM, 1.0f + EPSLMO_ + SIGMA_, bR, bC, bP);
    gemmT(sM, sA, sT);
    __syncthreads();
    gemmS(sA, sT, sS);
    if (t < 64) su0[t] = dotA(sM, t, sg);
    __syncthreads();

    const int row = t >> 1, h = t & 1;
    float lo = 0.f, hi = 0.f, cx0 = 0.f;
    if (t < 192){
        if (row < 64){ lo = 0.f; hi = INFINITY; cx0 = su0[row]; }
        else { int a = row - 64; lo = -INFINITY; hi = bp[a] * srv[a]; cx0 = dotA(sA, a, su0); }
    }
    unsigned long long G2[24];
    if (t < 192){
#pragma unroll
        for (int c2 = 0; c2 < 24; ++c2){
            int c0 = h*48 + 2*c2, c1 = c0 + 1;
            float g0, g1;
            if (row < 64){
                g0 = (c0 < 64) ? sM[row*68 + c0] : sT[row*36 + (c0-64)];
                g1 = (c1 < 64) ? sM[row*68 + c1] : sT[row*36 + (c1-64)];
            } else {
                int a = row - 64;
                g0 = (c0 < 64) ? sT[c0*36 + a] : sS[a*36 + (c0-64)];
                g1 = (c1 < 64) ? sT[c1*36 + a] : sS[a*36 + (c1-64)];
            }
            PACK2(G2[c2], g0, g1);
        }
    }
    __syncthreads();

    float z = fminf(fmaxf(0.f, lo), hi), y = 0.f;
    for (int it = 0; it < ITERS; ++it){
        float* vb = sv + (it & 1) * 96;
        if (t < 192 && h == 0) vb[row] = z - y;
        __syncthreads();
        const ulonglong2* v2 = (const ulonglong2*)vb + h*12;
        unsigned long long a0 = 0ull, a1 = 0ull, a2 = 0ull, a3 = 0ull;
#pragma unroll
        for (int c = 0; c < 12; ++c){
            ulonglong2 vv = v2[c];
            if (c & 1){ FMA2(a2, G2[2*c], vv.x); FMA2(a3, G2[2*c+1], vv.y); }
            else      { FMA2(a0, G2[2*c], vv.x); FMA2(a1, G2[2*c+1], vv.y); }
        }
        float x0, x1, x2, x3, x4, x5, x6, x7;
        UNPK2(x0, x1, a0); UNPK2(x2, x3, a1); UNPK2(x4, x5, a2); UNPK2(x6, x7, a3);
        float acc = ((x0+x1)+(x2+x3)) + ((x4+x5)+(x6+x7));
        acc += __shfl_xor_sync(0xFFFFFFFFu, acc, 1);
        float Cx = cx0 + acc;
        float zn = fminf(fmaxf(Cx + y, lo), hi);
        y += Cx - zn; z = zn;
    }
    __syncthreads();

    const float* vl = sv + ((ITERS-1) & 1) * 96;
    if (t < 64){
        float a = vl[t];
        for (int r = 0; r < 32; ++r) a += sA[r*68 + t] * vl[64+r];
        sd[t] = a;
    }
    __syncthreads();
    if (t < 64){
        float c_sol = su0[t] + dotA(sM, t, sd);
        out[(size_t)p*64 + t] = 0.9f * sx[t] + 0.1f * c_sol;
    }
}

// ---------------------------------------------------------------------------
extern "C" void kernel_launch(void* const* d_in, const int* in_sizes, int n_in,
                              void* d_out, int out_size)
{
    const float* xr = (const float*)d_in[0];
    const float* A  = (const float*)d_in[1];
    const float* b  = (const float*)d_in[2];
    const float* W1 = (const float*)d_in[3];
    const float* w2 = (const float*)d_in[4];
    float* out = (float*)d_out;

    const int a_smem = (2176 + 4352 + 2304 + 1152 + 256 + 256 + 128 + 128 + 16
                        + 208 + 68 + 68 + 64 + 128 + 128 + 8) * (int)sizeof(float);
    const int l_smem = (2176 + 4352 + 2304 + 1152 + 192 + 64 + 64 + 64 + 256
                        + 64 + 32 + 128 + 128 + 8) * (int)sizeof(float);

    cudaFuncSetAttribute(anchor_kernel, cudaFuncAttributeMaxDynamicSharedMemorySize, a_smem);
    cudaFuncSetAttribute(lmo_kernel,    cudaFuncAttributeMaxDynamicSharedMemorySize, l_smem);

    anchor_kernel<<<NPROB, TPB, a_smem>>>(xr, A, b);
    lmo_kernel<<<NPROB, TPB, l_smem>>>(A, b, W1, w2, out);
}

// round 9
// speedup vs baseline: 1.0012x; 1.0012x over previous
#include <cuda_runtime.h>
#include <math.h>

#define NPROB 4096
#define TPB   256
#define ITERS 80
static constexpr float SIGMA_  = 1e-6f;
static constexpr float EPSLMO_ = 1e-4f;

__device__ float g_xfeas[NPROB * 64];

#define FMA2(d,a,b)  asm("fma.rn.f32x2 %0, %1, %2, %0;" : "+l"(d) : "l"(a), "l"(b))
#define PACK2(d,x,y) asm("mov.b64 %0, {%1, %2};" : "=l"(d) : "f"(x), "f"(y))
#define UNPK2(x,y,v) asm("mov.b64 {%0, %1}, %2;" : "=f"(x), "=f"(y) : "l"(v))

__device__ __forceinline__ float dot4(float4 a, float4 b){
    return a.x*b.x + a.y*b.y + a.z*b.z + a.w*b.w;
}
__device__ __forceinline__ float dotA(const float* sA, int i, const float* v){
    const float4* a4 = (const float4*)(sA + i*68);
    const float4* v4 = (const float4*)v;
    float s = 0.f;
#pragma unroll
    for (int q = 0; q < 16; ++q) s += dot4(a4[q], v4[q]);
    return s;
}

// ---------------------------------------------------------------------------
// Register-resident GJ inverse of M = diag*I + A^T A (64x64), result -> sM.
// Thread t: row gi = t&63, cols [j0, j0+16), j0 = (t>>6)*16, in R[16].
// Pivot row chunks are consumed immediately (live pr = 1 float4) to keep
// register pressure under the 3-CTA (85 reg) cap.
// ---------------------------------------------------------------------------
__device__ __forceinline__ void gj64_reg(const float* sA, float* sM, float diag,
                                         float* bufRow, float* bufCol, float* bufPinv)
{
    const int t  = threadIdx.x;
    const int gi = t & 63;
    const int cb = t >> 6;
    const int j0 = cb << 4;

    float R[16];
#pragma unroll
    for (int l = 0; l < 16; ++l) R[l] = 0.f;
    for (int r = 0; r < 32; ++r){
        float  ag = sA[r*68 + gi];
        float4 a0 = *(const float4*)(sA + r*68 + j0);
        float4 a1 = *(const float4*)(sA + r*68 + j0 + 4);
        float4 a2 = *(const float4*)(sA + r*68 + j0 + 8);
        float4 a3 = *(const float4*)(sA + r*68 + j0 + 12);
        R[0]+=ag*a0.x; R[1]+=ag*a0.y; R[2]+=ag*a0.z; R[3]+=ag*a0.w;
        R[4]+=ag*a1.x; R[5]+=ag*a1.y; R[6]+=ag*a1.z; R[7]+=ag*a1.w;
        R[8]+=ag*a2.x; R[9]+=ag*a2.y; R[10]+=ag*a2.z; R[11]+=ag*a2.w;
        R[12]+=ag*a3.x; R[13]+=ag*a3.y; R[14]+=ag*a3.z; R[15]+=ag*a3.w;
    }
    if ((gi >> 4) == cb){
#pragma unroll
        for (int l = 0; l < 16; ++l) if ((gi & 15) == l) R[l] += diag;
    }
    if (gi == 0){
        *(float4*)(bufRow + j0)      = make_float4(R[0],R[1],R[2],R[3]);
        *(float4*)(bufRow + j0 + 4)  = make_float4(R[4],R[5],R[6],R[7]);
        *(float4*)(bufRow + j0 + 8)  = make_float4(R[8],R[9],R[10],R[11]);
        *(float4*)(bufRow + j0 + 12) = make_float4(R[12],R[13],R[14],R[15]);
        if (cb == 0) bufPinv[0] = __frcp_rn(R[0]);
    }
    if (cb == 0) bufCol[gi] = R[0];
    __syncthreads();

    for (int ko = 0; ko < 4; ++ko){
#pragma unroll
        for (int ki = 0; ki < 16; ++ki){
            const int k = ko*16 + ki;
            const int b = ki & 1;
            float pinv = bufPinv[b];
            float pc   = bufCol[b*64 + gi];
            const bool isk = (gi == k);
            float fac = isk ? pinv : (-pc * pinv);
            // R = isk ? pr*pinv : R - cp*pr   ==  R*(isk?0:1) + fac*pr
#pragma unroll
            for (int q = 0; q < 4; ++q){
                float4 p = *(const float4*)(bufRow + b*64 + j0 + 4*q);
                if (isk){
                    R[4*q+0] = p.x*fac; R[4*q+1] = p.y*fac;
                    R[4*q+2] = p.z*fac; R[4*q+3] = p.w*fac;
                } else {
                    R[4*q+0] += p.x*fac; R[4*q+1] += p.y*fac;
                    R[4*q+2] += p.z*fac; R[4*q+3] += p.w*fac;
                }
            }
            if (ko == cb) R[ki] = isk ? pinv : fac;
            if (k < 63){
                const int kn  = k + 1;
                const int bn  = kn & 1;
                const int kol = (ki == 15) ? (ko + 1) : ko;
                const int lnl = (ki + 1) & 15;
                if (gi == kn){
                    *(float4*)(bufRow + bn*64 + j0)      = make_float4(R[0],R[1],R[2],R[3]);
                    *(float4*)(bufRow + bn*64 + j0 + 4)  = make_float4(R[4],R[5],R[6],R[7]);
                    *(float4*)(bufRow + bn*64 + j0 + 8)  = make_float4(R[8],R[9],R[10],R[11]);
                    *(float4*)(bufRow + bn*64 + j0 + 12) = make_float4(R[12],R[13],R[14],R[15]);
                    if (kol == cb) bufPinv[bn] = __frcp_rn(R[lnl]);
                }
                if (kol == cb) bufCol[bn*64 + gi] = R[lnl];
            }
            __syncthreads();
        }
    }
    *(float4*)(sM + gi*68 + j0)      = make_float4(R[0],R[1],R[2],R[3]);
    *(float4*)(sM + gi*68 + j0 + 4)  = make_float4(R[4],R[5],R[6],R[7]);
    *(float4*)(sM + gi*68 + j0 + 8)  = make_float4(R[8],R[9],R[10],R[11]);
    *(float4*)(sM + gi*68 + j0 + 12) = make_float4(R[12],R[13],R[14],R[15]);
    __syncthreads();
}

// T (64x32, stride 36) = N * A^T
__device__ __forceinline__ void gemmT(const float* sM, const float* sA, float* sT)
{
    const int t  = threadIdx.x;
    const int i0 = (t >> 4) << 2;
    const int r0 = (t & 15) << 1;
    float acc[4][2] = {};
    for (int j = 0; j < 64; j += 4){
        float4 a0 = *(const float4*)(sA + r0*68     + j);
        float4 a1 = *(const float4*)(sA + (r0+1)*68 + j);
#pragma unroll
        for (int a = 0; a < 4; ++a){
            float4 nv = *(const float4*)(sM + (i0+a)*68 + j);
            acc[a][0] += dot4(nv, a0);
            acc[a][1] += dot4(nv, a1);
        }
    }
#pragma unroll
    for (int a = 0; a < 4; ++a){
        sT[(i0+a)*36 + r0]     = acc[a][0];
        sT[(i0+a)*36 + r0 + 1] = acc[a][1];
    }
}

// S (32x32, stride 36) = A * T
__device__ __forceinline__ void gemmS(const float* sA, const float* sT, float* sS)
{
    const int t  = threadIdx.x;
    const int r  = t >> 3;
    const int cb = (t & 7) << 2;
    float4 acc = make_float4(0.f,0.f,0.f,0.f);
    for (int i = 0; i < 64; ++i){
        float av  = sA[r*68 + i];
        float4 tv = *(const float4*)(sT + i*36 + cb);
        acc.x += av*tv.x; acc.y += av*tv.y; acc.z += av*tv.z; acc.w += av*tv.w;
    }
    *(float4*)(sS + r*36 + cb) = acc;
}

// ======================= ANCHOR: d=68 (Schur), K=100 (pad 104) ==============
__device__ __forceinline__ float gA(int r, int c, const float* sM, const float* sT,
                                    const float* sS, const float* sW, const float* sV,
                                    const float* sXi)
{
    if (c >= 100) return 0.f;
    if (r < 64){
        if (c < 64) return sM[r*68 + c];
        if (c < 92) return sT[r*36 + (c-64)];
        if (c < 96) return sT[r*36 + 28 + (c-92)] + sW[r*4 + (c-92)];
        return -sW[r*4 + (c-96)];
    }
    if (r < 92){ int i = r-64;
        if (c < 64) return sT[c*36 + i];
        if (c < 92) return sS[i*36 + (c-64)];
        if (c < 96) return sS[i*36 + 28 + (c-92)] + sV[i*4 + (c-92)];
        return -sV[i*4 + (c-96)];
    }
    if (r < 96){ int m = r-92, i = 28+m;
        if (c < 64) return sT[c*36 + i] + sW[c*4 + m];
        if (c < 92) return sS[i*36 + (c-64)] + sV[(c-64)*4 + m];
        if (c < 96){ int j = c-92;
            return sS[i*36 + 28 + j] + sV[i*4 + j] + sV[(28+j)*4 + m] + sXi[m*4 + j]; }
        { int j = c-96; return -sV[i*4 + j] - sXi[m*4 + j]; }
    }
    { int m = r-96;
        if (c < 64) return -sW[c*4 + m];
        if (c < 92) return -sV[(c-64)*4 + m];
        if (c < 96){ int j = c-92; return -sV[(28+j)*4 + m] - sXi[m*4 + j]; }
        { int j = c-96; return sXi[m*4 + j]; }
    }
}

__global__ void __launch_bounds__(TPB, 3)
anchor_kernel(const float* __restrict__ xr, const float* __restrict__ Ain,
              const float* __restrict__ bin)
{
    extern __shared__ float sm[];
    float* sA  = sm;             // 32*68
    float* sM  = sA  + 2176;     // 64*68
    float* sT  = sM  + 4352;     // 64*36
    float* sS  = sT  + 2304;     // 32*36
    float* sY  = sS  + 1152;     // 64*4
    float* sW  = sY  + 256;      // 64*4
    float* sU  = sW  + 256;      // 32*4
    float* sV  = sU  + 128;      // 32*4
    float* sXi = sV  + 128;      // 16
    float* sv  = sXi + 16;       // 2*104
    float* su0 = sv  + 208;      // 68
    float* sdx = su0 + 68;       // 68
    float* sxr = sdx + 68;       // 64
    float* bR  = sxr + 64;       // 128
    float* bC  = bR  + 128;      // 128
    float* bP  = bC  + 128;      // 2 + pad

    const int p = blockIdx.x;
    const int t = threadIdx.x;
    const float* Ap = Ain + (size_t)p * 2048;
    const float* bp = bin + (size_t)p * 32;

    for (int e = t; e < 2048; e += TPB) sA[(e>>6)*68 + (e&63)] = Ap[e];
    if (t < 64) sxr[t] = xr[(size_t)p*64 + t];
    if (t >= 64 && t < 72){ int q = t-64; sv[100 + (q&3) + (q>>2)*104] = 0.f; }
    __syncthreads();

    gj64_reg(sA, sM, 2.0f + SIGMA_, bR, bC, bP);
    gemmT(sM, sA, sT);
    __syncthreads();
    gemmS(sA, sT, sS);
    __syncthreads();

    if (t == 0){
        float X[4][4];
        for (int m = 0; m < 4; ++m)
            for (int j = 0; j < 4; ++j)
                X[m][j] = ((m==j) ? (4.0f+SIGMA_) : 0.f) - sS[(28+m)*36 + 28 + j];
        for (int k = 0; k < 4; ++k){
            float pinv = 1.0f / X[k][k];
            for (int j = 0; j < 4; ++j) if (j != k) X[k][j] *= pinv;
            X[k][k] = pinv;
            for (int i = 0; i < 4; ++i) if (i != k){
                float f = X[i][k];
                for (int j = 0; j < 4; ++j) if (j != k) X[i][j] -= f * X[k][j];
                X[i][k] = -f * pinv;
            }
        }
        for (int m = 0; m < 4; ++m)
            for (int j = 0; j < 4; ++j) sXi[m*4+j] = X[m][j];
    }
    __syncthreads();
    if (t < 64){
        float y[4];
#pragma unroll
        for (int m = 0; m < 4; ++m){ y[m] = -sT[t*36 + 28 + m]; sY[t*4+m] = y[m]; }
#pragma unroll
        for (int m = 0; m < 4; ++m){
            float a = 0.f;
#pragma unroll
            for (int j = 0; j < 4; ++j) a += y[j] * sXi[j*4+m];
            sW[t*4+m] = a;
        }
    } else if (t < 96){
        int r = t - 64;
        float u[4];
#pragma unroll
        for (int m = 0; m < 4; ++m){ u[m] = -sS[r*36 + 28 + m]; sU[r*4+m] = u[m]; }
#pragma unroll
        for (int m = 0; m < 4; ++m){
            float a = 0.f;
#pragma unroll
            for (int j = 0; j < 4; ++j) a += u[j] * sXi[j*4+m];
            sV[r*4+m] = a;
        }
    }
    __syncthreads();
    for (int e = t; e < 4096; e += TPB){
        int i = e >> 6, j = e & 63; float a = 0.f;
#pragma unroll
        for (int m = 0; m < 4; ++m) a += sW[i*4+m] * sY[j*4+m];
        sM[i*68 + j] += a;
    }
    for (int e = t; e < 2048; e += TPB){
        int i = e >> 5, a0 = e & 31; float a = 0.f;
#pragma unroll
        for (int m = 0; m < 4; ++m) a += sW[i*4+m] * sU[a0*4+m];
        sT[i*36 + a0] += a;
    }
    for (int e = t; e < 1024; e += TPB){
        int r = e >> 5, c = e & 31; float a = 0.f;
#pragma unroll
        for (int m = 0; m < 4; ++m) a += sV[r*4+m] * sU[c*4+m];
        sS[r*36 + c] += a;
    }
    __syncthreads();
    if (t < 64) su0[t] = dotA(sM, t, sxr);
    else if (t < 68){
        int m = t - 64; float a = 0.f;
        for (int j = 0; j < 64; ++j) a -= sW[j*4+m] * sxr[j];
        su0[64+m] = a;
    }
    __syncthreads();

    const int row = t >> 1, h = t & 1;
    float lo = 0.f, hi = 0.f, cx0 = 0.f;
    if (t < 200){
        if (row < 64){ lo = 0.f; hi = INFINITY; cx0 = su0[row]; }
        else if (row < 92){ int i = row-64; lo = -INFINITY; hi = bp[i]; cx0 = dotA(sA, i, su0); }
        else if (row < 96){ int m = row-92; int i = 28+m;
            lo = -INFINITY; hi = bp[i]; cx0 = dotA(sA, i, su0) - su0[64+m]; }
        else { int m = row-96; lo = 0.f; hi = INFINITY; cx0 = su0[64+m]; }
    }
    unsigned long long G2[26];
    if (t < 200){
#pragma unroll
        for (int c2 = 0; c2 < 26; ++c2){
            float g0 = gA(row, h*52 + 2*c2,     sM, sT, sS, sW, sV, sXi);
            float g1 = gA(row, h*52 + 2*c2 + 1, sM, sT, sS, sW, sV, sXi);
            PACK2(G2[c2], g0, g1);
        }
    }
    __syncthreads();

    float z = fminf(fmaxf(0.f, lo), hi), y = 0.f;
    for (int it = 0; it < ITERS; ++it){
        float* vb = sv + (it & 1) * 104;
        if (t < 200 && h == 0) vb[row] = z - y;
        __syncthreads();
        const ulonglong2* v2 = (const ulonglong2*)vb + h*13;
        unsigned long long a0 = 0ull, a1 = 0ull, a2 = 0ull, a3 = 0ull;
#pragma unroll
        for (int c = 0; c < 13; ++c){
            ulonglong2 vv = v2[c];
            if (c & 1){ FMA2(a2, G2[2*c], vv.x); FMA2(a3, G2[2*c+1], vv.y); }
            else      { FMA2(a0, G2[2*c], vv.x); FMA2(a1, G2[2*c+1], vv.y); }
        }
        float x0, x1, x2, x3, x4, x5, x6, x7;
        UNPK2(x0, x1, a0); UNPK2(x2, x3, a1); UNPK2(x4, x5, a2); UNPK2(x6, x7, a3);
        float acc = ((x0+x1)+(x2+x3)) + ((x4+x5)+(x6+x7));
        acc += __shfl_xor_sync(0xFFFFFFFFu, acc, 1);
        float Cx = cx0 + acc;
        float zn = fminf(fmaxf(Cx + y, lo), hi);
        y += Cx - zn; z = zn;
    }
    __syncthreads();

    const float* vl = sv + ((ITERS-1) & 1) * 104;
    if (t < 64){
        float a = vl[t];
        for (int r = 0; r < 28; ++r) a += sA[r*68 + t] * vl[64+r];
#pragma unroll
        for (int r = 28; r < 32; ++r) a += sA[r*68 + t] * vl[92 + (r-28)];
        sdx[t] = a;
    } else if (t < 68){
        int m = t - 64; sdx[64+m] = vl[96+m] - vl[92+m];
    }
    __syncthreads();
    if (t < 64){
        float a = su0[t] + dotA(sM, t, sdx);
#pragma unroll
        for (int m = 0; m < 4; ++m) a -= sW[t*4+m] * sdx[64+m];
        g_xfeas[(size_t)p*64 + t] = a;
    }
}

// ======================= LMO: d=64, K=96 ====================================
__global__ void __launch_bounds__(TPB, 3)
lmo_kernel(const float* __restrict__ Ain, const float* __restrict__ bin,
           const float* __restrict__ W1, const float* __restrict__ w2,
           float* __restrict__ out)
{
    extern __shared__ float sm[];
    float* sA  = sm;             // 32*68 (normalized)
    float* sM  = sA  + 2176;     // 64*68
    float* sT  = sM  + 4352;     // 64*36
    float* sS  = sT  + 2304;     // 32*36
    float* sv  = sS  + 1152;     // 2*96
    float* su0 = sv  + 192;      // 64
    float* sd  = su0 + 64;       // 64
    float* sx  = sd  + 64;       // 64
    float* shb = sx  + 64;       // 256
    float* sg  = shb + 256;      // 64
    float* srv = sg  + 64;       // 32
    float* bR  = srv + 32;       // 128
    float* bC  = bR  + 128;      // 128
    float* bP  = bC  + 128;      // 2 + pad

    const int p = blockIdx.x;
    const int t = threadIdx.x;
    const float* Ap = Ain + (size_t)p * 2048;
    const float* bp = bin + (size_t)p * 32;

    for (int e = t; e < 2048; e += TPB) sA[(e>>6)*68 + (e&63)] = Ap[e];
    if (t < 64) sx[t] = g_xfeas[(size_t)p*64 + t];
    __syncthreads();

    if (t < 32){
        float ss = 0.f;
        const float* Ar = sA + t*68;
        for (int i = 0; i < 64; ++i) ss += Ar[i]*Ar[i];
        srv[t] = 1.0f / fmaxf(sqrtf(ss), 1e-12f);
    }
    {
        float a = 0.f;
        for (int i = 0; i < 64; ++i) a += sx[i] * W1[i*256 + t];
        float hh = tanhf(a);
        shb[t] = (1.f - hh*hh) * w2[t];
    }
    __syncthreads();
    for (int e = t; e < 2048; e += TPB){
        int r = e >> 6;
        sA[r*68 + (e&63)] *= srv[r];
    }
    {
        int wid = t >> 5, lane = t & 31;
        for (int rr = 0; rr < 8; ++rr){
            int i = wid*8 + rr;
            const float* Wr = W1 + i*256;
            float a = 0.f;
#pragma unroll
            for (int k = 0; k < 8; ++k) a += Wr[k*32 + lane] * shb[k*32 + lane];
#pragma unroll
            for (int o = 16; o; o >>= 1) a += __shfl_xor_sync(0xFFFFFFFFu, a, o);
            if (lane == 0) sg[i] = a;
        }
    }
    __syncthreads();

    gj64_reg(sA, sM, 1.0f + EPSLMO_ + SIGMA_, bR, bC, bP);
    gemmT(sM, sA, sT);
    __syncthreads();
    gemmS(sA, sT, sS);
    if (t < 64) su0[t] = dotA(sM, t, sg);
    __syncthreads();

    const int row = t >> 1, h = t & 1;
    float lo = 0.f, hi = 0.f, cx0 = 0.f;
    if (t < 192){
        if (row < 64){ lo = 0.f; hi = INFINITY; cx0 = su0[row]; }
        else { int a = row - 64; lo = -INFINITY; hi = bp[a] * srv[a]; cx0 = dotA(sA, a, su0); }
    }
    unsigned long long G2[24];
    if (t < 192){
#pragma unroll
        for (int c2 = 0; c2 < 24; ++c2){
            int c0 = h*48 + 2*c2, c1 = c0 + 1;
            float g0, g1;
            if (row < 64){
                g0 = (c0 < 64) ? sM[row*68 + c0] : sT[row*36 + (c0-64)];
                g1 = (c1 < 64) ? sM[row*68 + c1] : sT[row*36 + (c1-64)];
            } else {
                int a = row - 64;
                g0 = (c0 < 64) ? sT[c0*36 + a] : sS[a*36 + (c0-64)];
                g1 = (c1 < 64) ? sT[c1*36 + a] : sS[a*36 + (c1-64)];
            }
            PACK2(G2[c2], g0, g1);
        }
    }
    __syncthreads();

    float z = fminf(fmaxf(0.f, lo), hi), y = 0.f;
    for (int it = 0; it < ITERS; ++it){
        float* vb = sv + (it & 1) * 96;
        if (t < 192 && h == 0) vb[row] = z - y;
        __syncthreads();
        const ulonglong2* v2 = (const ulonglong2*)vb + h*12;
        unsigned long long a0 = 0ull, a1 = 0ull, a2 = 0ull, a3 = 0ull;
#pragma unroll
        for (int c = 0; c < 12; ++c){
            ulonglong2 vv = v2[c];
            if (c & 1){ FMA2(a2, G2[2*c], vv.x); FMA2(a3, G2[2*c+1], vv.y); }
            else      { FMA2(a0, G2[2*c], vv.x); FMA2(a1, G2[2*c+1], vv.y); }
        }
        float x0, x1, x2, x3, x4, x5, x6, x7;
        UNPK2(x0, x1, a0); UNPK2(x2, x3, a1); UNPK2(x4, x5, a2); UNPK2(x6, x7, a3);
        float acc = ((x0+x1)+(x2+x3)) + ((x4+x5)+(x6+x7));
        acc += __shfl_xor_sync(0xFFFFFFFFu, acc, 1);
        float Cx = cx0 + acc;
        float zn = fminf(fmaxf(Cx + y, lo), hi);
        y += Cx - zn; z = zn;
    }
    __syncthreads();

    const float* vl = sv + ((ITERS-1) & 1) * 96;
    if (t < 64){
        float a = vl[t];
        for (int r = 0; r < 32; ++r) a += sA[r*68 + t] * vl[64+r];
        sd[t] = a;
    }
    __syncthreads();
    if (t < 64){
        float c_sol = su0[t] + dotA(sM, t, sd);
        out[(size_t)p*64 + t] = 0.9f * sx[t] + 0.1f * c_sol;
    }
}

// ---------------------------------------------------------------------------
extern "C" void kernel_launch(void* const* d_in, const int* in_sizes, int n_in,
                              void* d_out, int out_size)
{
    const float* xr = (const float*)d_in[0];
    const float* A  = (const float*)d_in[1];
    const float* b  = (const float*)d_in[2];
    const float* W1 = (const float*)d_in[3];
    const float* w2 = (const float*)d_in[4];
    float* out = (float*)d_out;

    const int a_smem = (2176 + 4352 + 2304 + 1152 + 256 + 256 + 128 + 128 + 16
                        + 208 + 68 + 68 + 64 + 128 + 128 + 8) * (int)sizeof(float);
    const int l_smem = (2176 + 4352 + 2304 + 1152 + 192 + 64 + 64 + 64 + 256
                        + 64 + 32 + 128 + 128 + 8) * (int)sizeof(float);

    cudaFuncSetAttribute(anchor_kernel, cudaFuncAttributeMaxDynamicSharedMemorySize, a_smem);
    cudaFuncSetAttribute(lmo_kernel,    cudaFuncAttributeMaxDynamicSharedMemorySize, l_smem);

    anchor_kernel<<<NPROB, TPB, a_smem>>>(xr, A, b);
    lmo_kernel<<<NPROB, TPB, l_smem>>>(A, b, W1, w2, out);
}